// round 14
// baseline (speedup 1.0000x reference)
#include <cuda_runtime.h>
#include <math.h>

// Problem constants
#define Hd 512
#define L 4096
#define B 8
#define N2 32
#define HN (Hd * N2)
#define T 64            // chunk length
#define NCH (L / T)     // 64 chunks per sequence
#define CB (NCH * B)    // 512 chunk-rows
#define Q 64            // 2*N2 (re block + im block)
#define BL (B * L)      // 32768
#define QTR (CB / 4)    // 128 cb per corr block
#define NCQ (NCH / 4)   // 16 chunks per quarter
#define CBPQ 132        // padded locS row stride (floats)
#define XRP 132         // padded xrs row stride
#define STP 66          // stg row stride
#define NCC 4           // chunks per k_out block (processed in pairs)

typedef unsigned long long u64;

__device__ __forceinline__ u64 pk2(float lo, float hi) {
    u64 r; asm("mov.b64 %0, {%1, %2};" : "=l"(r) : "f"(lo), "f"(hi)); return r;
}
__device__ __forceinline__ float2 upk2(u64 v) {
    float2 f; asm("mov.b64 {%0, %1}, %2;" : "=f"(f.x), "=f"(f.y) : "l"(v)); return f;
}
__device__ __forceinline__ u64 fma2(u64 a, u64 b, u64 c) {
    u64 d; asm("fma.rn.f32x2 %0, %1, %2, %3;" : "=l"(d) : "l"(a), "l"(b), "l"(c)); return d;
}

// ---------------------------------------------------------------------------
// Device-global parameter / scratch arrays
// ---------------------------------------------------------------------------
__device__ float g_dATre[HN], g_dATim[HN];                  // dA^T (double-derived)
__device__ __align__(16) float g_E[Hd * T * Q];             // [h][tau][q]: dA^{T-1-tau} dB
__device__ __align__(16) float g_W[Hd * Q * T];             // [h][q][t]
__device__ float g_K[Hd * T];                               // conv kernel
__device__ __align__(16) float g_xT[(size_t)Hd * BL];       // transposed x: [h][b*L+t]
__device__ __align__(16) float g_loc[(size_t)Hd * Q * CB];  // [h][q][cb]
__device__ __align__(16) float g_corr[(size_t)Hd * CB * T]; // [h][cb][t]
__device__ float g_qre[HN * 32], g_qim[HN * 32];            // quarter carry-in states

// ---------------------------------------------------------------------------
// K0 (fused): per-h discretization, E table, W table (+transpose), K kernel.
// ---------------------------------------------------------------------------
__global__ void __launch_bounds__(32) k_prep(const float* __restrict__ log_dt,
                                             const float* __restrict__ arl,
                                             const float* __restrict__ aim,
                                             const float* __restrict__ Bre,
                                             const float* __restrict__ Bim,
                                             const float* __restrict__ Cre,
                                             const float* __restrict__ Cim) {
    __shared__ float wt[T * 68];   // [t][q]
    const int h = blockIdx.x;
    const int n = threadIdx.x;
    const int i = h * 32 + n;
    float dt   = expf(log_dt[h]);
    float are  = -expf(arl[i]);
    float aimv = aim[i];
    float zre = are * dt, zim = aimv * dt;
    float sz, cz; sincosf(zim, &sz, &cz);
    float ez = expf(zre);
    float dre = ez * cz, dimv = ez * sz;   // dA
    float sh = sinf(0.5f * zim);
    float em1re = expm1f(zre) * cz - 2.0f * sh * sh;
    float em1im = ez * sz;
    float inv = 1.0f / (are * are + aimv * aimv);
    float fre = (em1re * are + em1im * aimv) * inv;
    float fim = (em1im * are - em1re * aimv) * inv;
    float bre0 = Bre[i], bim0 = Bim[i];
    float dbre = bre0 * fre - bim0 * fim;
    float dbim = bre0 * fim + bim0 * fre;
    float c2re  =  2.0f * Cre[i];
    float c2imN = -2.0f * Cim[i];
    double zred = (double)are * (double)dt * (double)T;
    double zimd = (double)aimv * (double)dt * (double)T;
    double ezd = exp(zred);
    g_dATre[i] = (float)(ezd * cos(zimd));
    g_dATim[i] = (float)(ezd * sin(zimd));
    float pre = dbre, pim = dbim;
    float cre0 = Cre[i], cim0 = Cim[i];
    float wre = cre0 * dre - cim0 * dimv;
    float wim = cre0 * dimv + cim0 * dre;
    for (int l = 0; l < T; ++l) {
        g_E[((size_t)h * T + (T - 1 - l)) * Q + n]      = pre;
        g_E[((size_t)h * T + (T - 1 - l)) * Q + 32 + n] = pim;
        wt[l * 68 + n]      =  2.0f * wre;
        wt[l * 68 + 32 + n] = -2.0f * wim;
        float kl = fmaf(c2re, pre, c2imN * pim);
        kl += __shfl_xor_sync(0xffffffffu, kl, 1);
        kl += __shfl_xor_sync(0xffffffffu, kl, 2);
        kl += __shfl_xor_sync(0xffffffffu, kl, 4);
        kl += __shfl_xor_sync(0xffffffffu, kl, 8);
        kl += __shfl_xor_sync(0xffffffffu, kl, 16);
        if (n == 0) g_K[h * T + l] = kl;
        float tre = pre * dre - pim * dimv; pim = pre * dimv + pim * dre; pre = tre;
        float ure = wre * dre - wim * dimv; wim = wre * dimv + wim * dre; wre = ure;
    }
    __syncthreads();
    for (int k = n; k < Q * T / 4; k += 32) {
        int q = k >> 4, tq = (k & 15) * 4;
        float4 v = make_float4(wt[(tq + 0) * 68 + q], wt[(tq + 1) * 68 + q],
                               wt[(tq + 2) * 68 + q], wt[(tq + 3) * 68 + q]);
        *reinterpret_cast<float4*>(&g_W[((size_t)h * Q + q) * T + tq]) = v;
    }
}

// ---------------------------------------------------------------------------
// K-tr: transpose x [bt][h] -> xT [h][bt], 64x64 tiles, float4 global I/O
// ---------------------------------------------------------------------------
__global__ void __launch_bounds__(256) k_tr(const float* __restrict__ x) {
    __shared__ float tile[64 * 65];
    const int bt0 = blockIdx.x * 64;
    const int h0  = blockIdx.y * 64;
    const int tid = threadIdx.x;
    #pragma unroll
    for (int it = 0; it < 4; ++it) {
        int idx = tid + it * 256;           // [0,1024)
        int r = idx >> 4, q = idx & 15;
        float4 v = *reinterpret_cast<const float4*>(
            &x[(size_t)(bt0 + r) * Hd + h0 + q * 4]);
        float* tr = &tile[r * 65 + q * 4];
        tr[0] = v.x; tr[1] = v.y; tr[2] = v.z; tr[3] = v.w;
    }
    __syncthreads();
    #pragma unroll
    for (int it = 0; it < 4; ++it) {
        int idx = tid + it * 256;
        int hh = idx >> 4, rq = idx & 15;
        float4 v = make_float4(tile[(rq * 4 + 0) * 65 + hh],
                               tile[(rq * 4 + 1) * 65 + hh],
                               tile[(rq * 4 + 2) * 65 + hh],
                               tile[(rq * 4 + 3) * 65 + hh]);
        *reinterpret_cast<float4*>(&g_xT[(size_t)(h0 + hh) * BL + bt0 + rq * 4]) = v;
    }
}

// ---------------------------------------------------------------------------
// K1: loc[h][q][cb] = sum_tau E[h][tau][q] * x[cb][tau]
// ---------------------------------------------------------------------------
__global__ void __launch_bounds__(256) k_loc() {
    extern __shared__ float sm[];
    float* Es  = sm;                // [64][64] 16KB
    float* xrs = sm + T * Q;        // [64][XRP] 33.8KB
    const int h = blockIdx.x;
    const int cb0 = blockIdx.y * 128;
    const int tid = threadIdx.x;
    for (int k = tid; k < T * Q / 4; k += 256)
        reinterpret_cast<float4*>(Es)[k] =
            reinterpret_cast<const float4*>(g_E + (size_t)h * T * Q)[k];
    for (int k = tid; k < 128 * T; k += 256) {
        int c2 = k >> 6, tau = k & 63;
        int cb = cb0 + c2, b = cb & 7, c = cb >> 3;
        xrs[tau * XRP + c2] = g_xT[(size_t)h * BL + b * L + c * T + tau];
    }
    __syncthreads();
    const int cc = tid & 31, w = tid >> 5, q0 = w * 8;
    u64 acc[4][4];
    #pragma unroll
    for (int a = 0; a < 4; ++a)
        #pragma unroll
        for (int p = 0; p < 4; ++p) acc[a][p] = 0ull;
    #pragma unroll 4
    for (int tau = 0; tau < T; ++tau) {
        float4 xv = *reinterpret_cast<const float4*>(&xrs[tau * XRP + cc * 4]);
        ulonglong2 ea = *reinterpret_cast<const ulonglong2*>(&Es[tau * Q + q0]);
        ulonglong2 eb = *reinterpret_cast<const ulonglong2*>(&Es[tau * Q + q0 + 4]);
        u64 xx;
        xx = pk2(xv.x, xv.x);
        acc[0][0] = fma2(ea.x, xx, acc[0][0]); acc[0][1] = fma2(ea.y, xx, acc[0][1]);
        acc[0][2] = fma2(eb.x, xx, acc[0][2]); acc[0][3] = fma2(eb.y, xx, acc[0][3]);
        xx = pk2(xv.y, xv.y);
        acc[1][0] = fma2(ea.x, xx, acc[1][0]); acc[1][1] = fma2(ea.y, xx, acc[1][1]);
        acc[1][2] = fma2(eb.x, xx, acc[1][2]); acc[1][3] = fma2(eb.y, xx, acc[1][3]);
        xx = pk2(xv.z, xv.z);
        acc[2][0] = fma2(ea.x, xx, acc[2][0]); acc[2][1] = fma2(ea.y, xx, acc[2][1]);
        acc[2][2] = fma2(eb.x, xx, acc[2][2]); acc[2][3] = fma2(eb.y, xx, acc[2][3]);
        xx = pk2(xv.w, xv.w);
        acc[3][0] = fma2(ea.x, xx, acc[3][0]); acc[3][1] = fma2(ea.y, xx, acc[3][1]);
        acc[3][2] = fma2(eb.x, xx, acc[3][2]); acc[3][3] = fma2(eb.y, xx, acc[3][3]);
    }
    #pragma unroll
    for (int p = 0; p < 4; ++p) {
        float2 f0 = upk2(acc[0][p]), f1 = upk2(acc[1][p]);
        float2 f2 = upk2(acc[2][p]), f3 = upk2(acc[3][p]);
        int q = q0 + 2 * p;
        *reinterpret_cast<float4*>(&g_loc[((size_t)h * Q + q) * CB + cb0 + cc * 4]) =
            make_float4(f0.x, f1.x, f2.x, f3.x);
        *reinterpret_cast<float4*>(&g_loc[((size_t)h * Q + q + 1) * CB + cb0 + cc * 4]) =
            make_float4(f0.y, f1.y, f2.y, f3.y);
    }
}

// ---------------------------------------------------------------------------
// K-mid: quarter-boundary carry states.
// ---------------------------------------------------------------------------
__global__ void k_mid() {
    int i = blockIdx.x * 256 + threadIdx.x;   // [0, HN*8)
    if (i >= HN * 8) return;
    int b = i & 7, n = (i >> 3) & 31, h = i >> 8;
    float aRe = g_dATre[h * 32 + n], aIm = g_dATim[h * 32 + n];
    const float* gr = &g_loc[((size_t)h * Q + n) * CB + b];
    const float* gi = &g_loc[((size_t)h * Q + 32 + n) * CB + b];
    float cre = 0.0f, cim = 0.0f;
    #pragma unroll
    for (int qi = 0; qi < 3; ++qi) {
        #pragma unroll
        for (int c = 0; c < NCQ; ++c) {
            float lre = __ldg(gr + (qi * NCQ + c) * 8);
            float lim = __ldg(gi + (qi * NCQ + c) * 8);
            float nre = fmaf(aRe, cre, fmaf(-aIm, cim, lre));
            float nim = fmaf(aIm, cre, fmaf(aRe, cim, lim));
            cre = nre; cim = nim;
        }
        g_qre[(h * 32 + n) * 32 + qi * 8 + b] = cre;
        g_qim[(h * 32 + n) * 32 + qi * 8 + b] = cim;
    }
}

// ---------------------------------------------------------------------------
// K2: carry-scan (16 chunks) + correction GEMM per quarter.
// ---------------------------------------------------------------------------
__global__ void __launch_bounds__(256) k_corrf(float* __restrict__ out, int stateMode) {
    extern __shared__ float sm[];
    float* locS = sm;                    // 64*132 = 33.8KB
    float* Ws   = sm + Q * CBPQ;         // 16KB
    float* stg  = Ws + Q * T;            // 64*66 = 16.9KB
    const int h = blockIdx.x;
    const int qtr = blockIdx.y;
    const int cbh = qtr * QTR;
    const int tid = threadIdx.x;
    for (int k = tid; k < Q * T / 4; k += 256)
        reinterpret_cast<float4*>(Ws)[k] =
            reinterpret_cast<const float4*>(g_W + (size_t)h * Q * T)[k];
    for (int k = tid; k < Q * QTR / 4; k += 256) {
        int q = k >> 5, c4 = k & 31;
        *reinterpret_cast<float4*>(&locS[q * CBPQ + c4 * 4]) =
            *reinterpret_cast<const float4*>(&g_loc[((size_t)h * Q + q) * CB + cbh + c4 * 4]);
    }
    __syncthreads();
    {
        int n = tid >> 3, b = tid & 7;
        float aRe = g_dATre[h * 32 + n], aIm = g_dATim[h * 32 + n];
        float cre = 0.0f, cim = 0.0f;
        if (qtr > 0) {
            cre = g_qre[(h * 32 + n) * 32 + (qtr - 1) * 8 + b];
            cim = g_qim[(h * 32 + n) * 32 + (qtr - 1) * 8 + b];
        }
        float* pr = &locS[n * CBPQ + b];
        float* pi = &locS[(32 + n) * CBPQ + b];
        #pragma unroll 4
        for (int c = 0; c < NCQ; ++c) {
            float lre = pr[c * 8], lim = pi[c * 8];
            pr[c * 8] = cre; pi[c * 8] = cim;
            float nre = fmaf(aRe, cre, fmaf(-aIm, cim, lre));
            float nim = fmaf(aIm, cre, fmaf(aRe, cim, lim));
            cre = nre; cim = nim;
        }
        if (qtr == 3 && stateMode > 0) {
            size_t ysEnd = (size_t)B * L * Hd;
            size_t idx = ((size_t)b * Hd + h) * N2 + n;
            out[ysEnd + idx] = cre;
            if (stateMode > 1) out[ysEnd + (size_t)B * Hd * N2 + idx] = cim;
        }
    }
    __syncthreads();
    const int cc = tid & 31, w = tid >> 5, t0 = w * 8;
    u64 acc[4][4];
    #pragma unroll
    for (int a = 0; a < 4; ++a)
        #pragma unroll
        for (int p = 0; p < 4; ++p) acc[a][p] = 0ull;
    #pragma unroll 4
    for (int q = 0; q < Q; ++q) {
        float4 sv = *reinterpret_cast<const float4*>(&locS[q * CBPQ + cc * 4]);
        ulonglong2 wa = *reinterpret_cast<const ulonglong2*>(&Ws[q * T + t0]);
        ulonglong2 wb = *reinterpret_cast<const ulonglong2*>(&Ws[q * T + t0 + 4]);
        u64 xx;
        xx = pk2(sv.x, sv.x);
        acc[0][0] = fma2(wa.x, xx, acc[0][0]); acc[0][1] = fma2(wa.y, xx, acc[0][1]);
        acc[0][2] = fma2(wb.x, xx, acc[0][2]); acc[0][3] = fma2(wb.y, xx, acc[0][3]);
        xx = pk2(sv.y, sv.y);
        acc[1][0] = fma2(wa.x, xx, acc[1][0]); acc[1][1] = fma2(wa.y, xx, acc[1][1]);
        acc[1][2] = fma2(wb.x, xx, acc[1][2]); acc[1][3] = fma2(wb.y, xx, acc[1][3]);
        xx = pk2(sv.z, sv.z);
        acc[2][0] = fma2(wa.x, xx, acc[2][0]); acc[2][1] = fma2(wa.y, xx, acc[2][1]);
        acc[2][2] = fma2(wb.x, xx, acc[2][2]); acc[2][3] = fma2(wb.y, xx, acc[2][3]);
        xx = pk2(sv.w, sv.w);
        acc[3][0] = fma2(wa.x, xx, acc[3][0]); acc[3][1] = fma2(wa.y, xx, acc[3][1]);
        acc[3][2] = fma2(wb.x, xx, acc[3][2]); acc[3][3] = fma2(wb.y, xx, acc[3][3]);
    }
    #pragma unroll
    for (int rnd = 0; rnd < 2; ++rnd) {
        if ((cc >> 4) == rnd) {
            #pragma unroll
            for (int a = 0; a < 4; ++a) {
                float* row = &stg[(cc * 4 + a - rnd * 64) * STP + t0];
                #pragma unroll
                for (int p = 0; p < 4; ++p) {
                    float2 f = upk2(acc[a][p]);
                    *reinterpret_cast<float2*>(&row[2 * p]) = f;
                }
            }
        }
        __syncthreads();
        for (int k = tid; k < 64 * T / 4; k += 256) {
            int r = k >> 4, tp = (k & 15) * 4;
            float2 a2 = *reinterpret_cast<const float2*>(&stg[r * STP + tp]);
            float2 b2 = *reinterpret_cast<const float2*>(&stg[r * STP + tp + 2]);
            *reinterpret_cast<float4*>(
                &g_corr[((size_t)h * CB + cbh + rnd * 64 + r) * T + tp]) =
                make_float4(a2.x, a2.y, b2.x, b2.y);
        }
        __syncthreads();
    }
}

// ---------------------------------------------------------------------------
// K4: output = causal conv(K,x) + corr + D*x, then exact GELU.
// Pair-balanced: warp w does octet w of chunk A (w+1 tiles) and octet 7-w of
// chunk B (8-w tiles) => 9 tiles per warp. grid (CB/NCC, Hd/32), block 256,
// dynamic smem (2 x-buffers + K + 2 corr buffers).
// ---------------------------------------------------------------------------
__global__ void __launch_bounds__(256) k_out(const float* __restrict__ x,
                                             const float* __restrict__ Dv,
                                             float* __restrict__ out) {
    extern __shared__ float smo[];
    float* xs0 = smo;                      // [32*133]
    float* xs1 = smo + 32 * 133;
    float* Ks  = smo + 2 * 32 * 133;       // [32*65]
    float* cs0 = Ks + 32 * 65;             // [32*65]
    float* cs1 = cs0 + 32 * 65;
    const int h0 = blockIdx.y * 32;
    const int tid = threadIdx.x;
    const int hh = tid & 31, w = tid >> 5;
    // one-time: zero pads + K table
    for (int k = tid; k < 32 * 63; k += 256) {
        int h2 = k & 31, r = k >> 5;
        xs0[h2 * 133 + r] = 0.0f;
        xs1[h2 * 133 + r] = 0.0f;
    }
    for (int k = tid; k < 32 * 64; k += 256) {
        int h2 = k & 31, l = k >> 5;
        Ks[h2 * 65 + l] = g_K[(h0 + h2) * T + l];
    }
    const float Dh = Dv[h0 + hh];
    const float* krow = &Ks[hh * 65];

    for (int pi = 0; pi < NCC / 2; ++pi) {
        const int cbA = blockIdx.x * NCC + 2 * pi;
        const int cbB = cbA + 1;
        const int bA = cbA & 7, cA = cbA >> 3;
        const int bB = cbB & 7, cB = cbB >> 3;
        __syncthreads();   // previous pair's compute done before overwriting
        for (int k = tid; k < 32 * 64; k += 256) {
            int h2 = k & 31, tt = k >> 5;
            xs0[h2 * 133 + 63 + tt] = x[((size_t)bA * L + cA * T + tt) * Hd + h0 + h2];
            xs1[h2 * 133 + 63 + tt] = x[((size_t)bB * L + cB * T + tt) * Hd + h0 + h2];
        }
        for (int k = tid; k < 2048; k += 256) {
            int h2 = k >> 6, tt = k & 63;
            cs0[h2 * 65 + tt] = g_corr[((size_t)(h0 + h2) * CB + cbA) * T + tt];
            cs1[h2 * 65 + tt] = g_corr[((size_t)(h0 + h2) * CB + cbB) * T + tt];
        }
        __syncthreads();

        #pragma unroll
        for (int e = 0; e < 2; ++e) {
            const int o  = e == 0 ? w : 7 - w;      // octet for this element
            const int t0 = o * 8;
            const float* xrow = (e == 0 ? xs0 : xs1) + hh * 133;
            const float* crow = (e == 0 ? cs0 : cs1) + hh * 65;
            const int b = e == 0 ? bA : bB;
            const int c = e == 0 ? cA : cB;

            u64 accp[4];
            #pragma unroll
            for (int p = 0; p < 4; ++p)
                accp[p] = pk2(crow[t0 + 2 * p], crow[t0 + 2 * p + 1]);

            for (int lt = 0; lt <= o; ++lt) {
                const int l0 = lt * 8;
                const int rb = 63 + t0 - l0 - 7;
                float xw[15];
                #pragma unroll
                for (int j = 0; j < 15; ++j) xw[j] = xrow[rb + j];
                u64 xwp[14];
                #pragma unroll
                for (int a = 0; a < 14; ++a) xwp[a] = pk2(xw[a], xw[a + 1]);
                #pragma unroll
                for (int i = 0; i < 8; ++i) {
                    float kv = krow[l0 + i];
                    u64 k2 = pk2(kv, kv);
                    accp[0] = fma2(k2, xwp[7 - i], accp[0]);
                    accp[1] = fma2(k2, xwp[9 - i], accp[1]);
                    accp[2] = fma2(k2, xwp[11 - i], accp[2]);
                    accp[3] = fma2(k2, xwp[13 - i], accp[3]);
                }
            }

            float acc[8];
            #pragma unroll
            for (int p = 0; p < 4; ++p) {
                float2 f = upk2(accp[p]);
                acc[2 * p] = f.x; acc[2 * p + 1] = f.y;
            }
            #pragma unroll
            for (int j = 0; j < 8; ++j) {
                float xv = xrow[63 + t0 + j];
                float yv = fmaf(Dh, xv, acc[j]);
                float g = 0.5f * yv * (1.0f + erff(yv * 0.70710678118654752f));
                out[((size_t)b * L + c * T + t0 + j) * Hd + h0 + hh] = g;
            }
        }
    }
}

// ---------------------------------------------------------------------------
// Launch
// ---------------------------------------------------------------------------
extern "C" void kernel_launch(void* const* d_in, const int* in_sizes, int n_in,
                              void* d_out, int out_size) {
    const float* x      = (const float*)d_in[0];
    const float* log_dt = (const float*)d_in[1];
    const float* arl    = (const float*)d_in[2];
    const float* aim    = (const float*)d_in[3];
    const float* Bre    = (const float*)d_in[4];
    const float* Bim    = (const float*)d_in[5];
    const float* Cre    = (const float*)d_in[6];
    const float* Cim    = (const float*)d_in[7];
    const float* Dv     = (const float*)d_in[8];
    float* out = (float*)d_out;

    const long long ysElems = (long long)B * L * Hd;   // 16,777,216
    const long long stN     = (long long)B * Hd * N2;  // 131,072
    int stateMode = 0;
    if ((long long)out_size >= ysElems + 2 * stN) stateMode = 2;
    else if ((long long)out_size >= ysElems + stN) stateMode = 1;

    const int locSmem  = (T * Q + T * XRP) * 4;                 // 50,176 B
    const int corrSmem = (Q * CBPQ + Q * T + 64 * STP) * 4;     // 67,072 B
    const int outSmem  = (2 * 32 * 133 + 3 * 32 * 65) * 4;      // 59,008 B
    static int attrDone = 0;
    if (!attrDone) {
        cudaFuncSetAttribute(k_loc, cudaFuncAttributeMaxDynamicSharedMemorySize, locSmem);
        cudaFuncSetAttribute(k_corrf, cudaFuncAttributeMaxDynamicSharedMemorySize, corrSmem);
        cudaFuncSetAttribute(k_out, cudaFuncAttributeMaxDynamicSharedMemorySize, outSmem);
        attrDone = 1;
    }

    k_prep<<<Hd, 32>>>(log_dt, arl, aim, Bre, Bim, Cre, Cim);
    k_tr<<<dim3(BL / 64, Hd / 64), 256>>>(x);
    k_loc<<<dim3(Hd, CB / 128), 256, locSmem>>>();
    k_mid<<<(HN * 8 + 255) / 256, 256>>>();
    k_corrf<<<dim3(Hd, 4), 256, corrSmem>>>(out, stateMode);
    k_out<<<dim3(CB / NCC, Hd / 32), 256, outSmem>>>(x, Dv, out);
}

// round 15
// speedup vs baseline: 1.0619x; 1.0619x over previous
#include <cuda_runtime.h>
#include <math.h>

// Problem constants
#define Hd 512
#define L 4096
#define B 8
#define N2 32
#define HN (Hd * N2)
#define T 64            // chunk length
#define NCH (L / T)     // 64 chunks per sequence
#define CB (NCH * B)    // 512 chunk-rows
#define Q 64            // 2*N2 (re block + im block)
#define BL (B * L)      // 32768
#define QTR (CB / 4)    // 128 cb per corr block
#define NCQ (NCH / 4)   // 16 chunks per quarter
#define CBPQ 132        // padded locS row stride (floats)
#define XRP 132         // padded xrs row stride
#define STP 66          // stg row stride
#define NCC 4           // chunks per k_out block (processed in pairs)
#define XSP 71          // slim xs row stride: 7 pad rows + 64 x rows

typedef unsigned long long u64;

__device__ __forceinline__ u64 pk2(float lo, float hi) {
    u64 r; asm("mov.b64 %0, {%1, %2};" : "=l"(r) : "f"(lo), "f"(hi)); return r;
}
__device__ __forceinline__ float2 upk2(u64 v) {
    float2 f; asm("mov.b64 {%0, %1}, %2;" : "=f"(f.x), "=f"(f.y) : "l"(v)); return f;
}
__device__ __forceinline__ u64 fma2(u64 a, u64 b, u64 c) {
    u64 d; asm("fma.rn.f32x2 %0, %1, %2, %3;" : "=l"(d) : "l"(a), "l"(b), "l"(c)); return d;
}

// ---------------------------------------------------------------------------
// Device-global parameter / scratch arrays
// ---------------------------------------------------------------------------
__device__ float g_dATre[HN], g_dATim[HN];                  // dA^T (double-derived)
__device__ __align__(16) float g_E[Hd * T * Q];             // [h][tau][q]: dA^{T-1-tau} dB
__device__ __align__(16) float g_W[Hd * Q * T];             // [h][q][t]
__device__ float g_K[Hd * T];                               // conv kernel
__device__ __align__(16) float g_xT[(size_t)Hd * BL];       // transposed x: [h][b*L+t]
__device__ __align__(16) float g_loc[(size_t)Hd * Q * CB];  // [h][q][cb]
__device__ __align__(16) float g_corr[(size_t)Hd * CB * T]; // [h][cb][t]
__device__ float g_qre[HN * 32], g_qim[HN * 32];            // quarter carry-in states

// ---------------------------------------------------------------------------
// K0 (fused): per-h discretization, E table, W table (+transpose), K kernel.
// ---------------------------------------------------------------------------
__global__ void __launch_bounds__(32) k_prep(const float* __restrict__ log_dt,
                                             const float* __restrict__ arl,
                                             const float* __restrict__ aim,
                                             const float* __restrict__ Bre,
                                             const float* __restrict__ Bim,
                                             const float* __restrict__ Cre,
                                             const float* __restrict__ Cim) {
    __shared__ float wt[T * 68];   // [t][q]
    const int h = blockIdx.x;
    const int n = threadIdx.x;
    const int i = h * 32 + n;
    float dt   = expf(log_dt[h]);
    float are  = -expf(arl[i]);
    float aimv = aim[i];
    float zre = are * dt, zim = aimv * dt;
    float sz, cz; sincosf(zim, &sz, &cz);
    float ez = expf(zre);
    float dre = ez * cz, dimv = ez * sz;   // dA
    float sh = sinf(0.5f * zim);
    float em1re = expm1f(zre) * cz - 2.0f * sh * sh;
    float em1im = ez * sz;
    float inv = 1.0f / (are * are + aimv * aimv);
    float fre = (em1re * are + em1im * aimv) * inv;
    float fim = (em1im * are - em1re * aimv) * inv;
    float bre0 = Bre[i], bim0 = Bim[i];
    float dbre = bre0 * fre - bim0 * fim;
    float dbim = bre0 * fim + bim0 * fre;
    float c2re  =  2.0f * Cre[i];
    float c2imN = -2.0f * Cim[i];
    double zred = (double)are * (double)dt * (double)T;
    double zimd = (double)aimv * (double)dt * (double)T;
    double ezd = exp(zred);
    g_dATre[i] = (float)(ezd * cos(zimd));
    g_dATim[i] = (float)(ezd * sin(zimd));
    float pre = dbre, pim = dbim;
    float cre0 = Cre[i], cim0 = Cim[i];
    float wre = cre0 * dre - cim0 * dimv;
    float wim = cre0 * dimv + cim0 * dre;
    for (int l = 0; l < T; ++l) {
        g_E[((size_t)h * T + (T - 1 - l)) * Q + n]      = pre;
        g_E[((size_t)h * T + (T - 1 - l)) * Q + 32 + n] = pim;
        wt[l * 68 + n]      =  2.0f * wre;
        wt[l * 68 + 32 + n] = -2.0f * wim;
        float kl = fmaf(c2re, pre, c2imN * pim);
        kl += __shfl_xor_sync(0xffffffffu, kl, 1);
        kl += __shfl_xor_sync(0xffffffffu, kl, 2);
        kl += __shfl_xor_sync(0xffffffffu, kl, 4);
        kl += __shfl_xor_sync(0xffffffffu, kl, 8);
        kl += __shfl_xor_sync(0xffffffffu, kl, 16);
        if (n == 0) g_K[h * T + l] = kl;
        float tre = pre * dre - pim * dimv; pim = pre * dimv + pim * dre; pre = tre;
        float ure = wre * dre - wim * dimv; wim = wre * dimv + wim * dre; wre = ure;
    }
    __syncthreads();
    for (int k = n; k < Q * T / 4; k += 32) {
        int q = k >> 4, tq = (k & 15) * 4;
        float4 v = make_float4(wt[(tq + 0) * 68 + q], wt[(tq + 1) * 68 + q],
                               wt[(tq + 2) * 68 + q], wt[(tq + 3) * 68 + q]);
        *reinterpret_cast<float4*>(&g_W[((size_t)h * Q + q) * T + tq]) = v;
    }
}

// ---------------------------------------------------------------------------
// K-tr: transpose x [bt][h] -> xT [h][bt], 64x64 tiles, float4 global I/O
// ---------------------------------------------------------------------------
__global__ void __launch_bounds__(256) k_tr(const float* __restrict__ x) {
    __shared__ float tile[64 * 65];
    const int bt0 = blockIdx.x * 64;
    const int h0  = blockIdx.y * 64;
    const int tid = threadIdx.x;
    #pragma unroll
    for (int it = 0; it < 4; ++it) {
        int idx = tid + it * 256;           // [0,1024)
        int r = idx >> 4, q = idx & 15;
        float4 v = *reinterpret_cast<const float4*>(
            &x[(size_t)(bt0 + r) * Hd + h0 + q * 4]);
        float* tr = &tile[r * 65 + q * 4];
        tr[0] = v.x; tr[1] = v.y; tr[2] = v.z; tr[3] = v.w;
    }
    __syncthreads();
    #pragma unroll
    for (int it = 0; it < 4; ++it) {
        int idx = tid + it * 256;
        int hh = idx >> 4, rq = idx & 15;
        float4 v = make_float4(tile[(rq * 4 + 0) * 65 + hh],
                               tile[(rq * 4 + 1) * 65 + hh],
                               tile[(rq * 4 + 2) * 65 + hh],
                               tile[(rq * 4 + 3) * 65 + hh]);
        *reinterpret_cast<float4*>(&g_xT[(size_t)(h0 + hh) * BL + bt0 + rq * 4]) = v;
    }
}

// ---------------------------------------------------------------------------
// K1: loc[h][q][cb] = sum_tau E[h][tau][q] * x[cb][tau]
// ---------------------------------------------------------------------------
__global__ void __launch_bounds__(256) k_loc() {
    extern __shared__ float sm[];
    float* Es  = sm;                // [64][64] 16KB
    float* xrs = sm + T * Q;        // [64][XRP] 33.8KB
    const int h = blockIdx.x;
    const int cb0 = blockIdx.y * 128;
    const int tid = threadIdx.x;
    for (int k = tid; k < T * Q / 4; k += 256)
        reinterpret_cast<float4*>(Es)[k] =
            reinterpret_cast<const float4*>(g_E + (size_t)h * T * Q)[k];
    for (int k = tid; k < 128 * T; k += 256) {
        int c2 = k >> 6, tau = k & 63;
        int cb = cb0 + c2, b = cb & 7, c = cb >> 3;
        xrs[tau * XRP + c2] = g_xT[(size_t)h * BL + b * L + c * T + tau];
    }
    __syncthreads();
    const int cc = tid & 31, w = tid >> 5, q0 = w * 8;
    u64 acc[4][4];
    #pragma unroll
    for (int a = 0; a < 4; ++a)
        #pragma unroll
        for (int p = 0; p < 4; ++p) acc[a][p] = 0ull;
    #pragma unroll 4
    for (int tau = 0; tau < T; ++tau) {
        float4 xv = *reinterpret_cast<const float4*>(&xrs[tau * XRP + cc * 4]);
        ulonglong2 ea = *reinterpret_cast<const ulonglong2*>(&Es[tau * Q + q0]);
        ulonglong2 eb = *reinterpret_cast<const ulonglong2*>(&Es[tau * Q + q0 + 4]);
        u64 xx;
        xx = pk2(xv.x, xv.x);
        acc[0][0] = fma2(ea.x, xx, acc[0][0]); acc[0][1] = fma2(ea.y, xx, acc[0][1]);
        acc[0][2] = fma2(eb.x, xx, acc[0][2]); acc[0][3] = fma2(eb.y, xx, acc[0][3]);
        xx = pk2(xv.y, xv.y);
        acc[1][0] = fma2(ea.x, xx, acc[1][0]); acc[1][1] = fma2(ea.y, xx, acc[1][1]);
        acc[1][2] = fma2(eb.x, xx, acc[1][2]); acc[1][3] = fma2(eb.y, xx, acc[1][3]);
        xx = pk2(xv.z, xv.z);
        acc[2][0] = fma2(ea.x, xx, acc[2][0]); acc[2][1] = fma2(ea.y, xx, acc[2][1]);
        acc[2][2] = fma2(eb.x, xx, acc[2][2]); acc[2][3] = fma2(eb.y, xx, acc[2][3]);
        xx = pk2(xv.w, xv.w);
        acc[3][0] = fma2(ea.x, xx, acc[3][0]); acc[3][1] = fma2(ea.y, xx, acc[3][1]);
        acc[3][2] = fma2(eb.x, xx, acc[3][2]); acc[3][3] = fma2(eb.y, xx, acc[3][3]);
    }
    #pragma unroll
    for (int p = 0; p < 4; ++p) {
        float2 f0 = upk2(acc[0][p]), f1 = upk2(acc[1][p]);
        float2 f2 = upk2(acc[2][p]), f3 = upk2(acc[3][p]);
        int q = q0 + 2 * p;
        *reinterpret_cast<float4*>(&g_loc[((size_t)h * Q + q) * CB + cb0 + cc * 4]) =
            make_float4(f0.x, f1.x, f2.x, f3.x);
        *reinterpret_cast<float4*>(&g_loc[((size_t)h * Q + q + 1) * CB + cb0 + cc * 4]) =
            make_float4(f0.y, f1.y, f2.y, f3.y);
    }
}

// ---------------------------------------------------------------------------
// K-mid: quarter-boundary carry states.
// ---------------------------------------------------------------------------
__global__ void k_mid() {
    int i = blockIdx.x * 256 + threadIdx.x;   // [0, HN*8)
    if (i >= HN * 8) return;
    int b = i & 7, n = (i >> 3) & 31, h = i >> 8;
    float aRe = g_dATre[h * 32 + n], aIm = g_dATim[h * 32 + n];
    const float* gr = &g_loc[((size_t)h * Q + n) * CB + b];
    const float* gi = &g_loc[((size_t)h * Q + 32 + n) * CB + b];
    float cre = 0.0f, cim = 0.0f;
    #pragma unroll
    for (int qi = 0; qi < 3; ++qi) {
        #pragma unroll
        for (int c = 0; c < NCQ; ++c) {
            float lre = __ldg(gr + (qi * NCQ + c) * 8);
            float lim = __ldg(gi + (qi * NCQ + c) * 8);
            float nre = fmaf(aRe, cre, fmaf(-aIm, cim, lre));
            float nim = fmaf(aIm, cre, fmaf(aRe, cim, lim));
            cre = nre; cim = nim;
        }
        g_qre[(h * 32 + n) * 32 + qi * 8 + b] = cre;
        g_qim[(h * 32 + n) * 32 + qi * 8 + b] = cim;
    }
}

// ---------------------------------------------------------------------------
// K2: carry-scan (16 chunks) + correction GEMM per quarter.
// ---------------------------------------------------------------------------
__global__ void __launch_bounds__(256) k_corrf(float* __restrict__ out, int stateMode) {
    extern __shared__ float sm[];
    float* locS = sm;                    // 64*132 = 33.8KB
    float* Ws   = sm + Q * CBPQ;         // 16KB
    float* stg  = Ws + Q * T;            // 64*66 = 16.9KB
    const int h = blockIdx.x;
    const int qtr = blockIdx.y;
    const int cbh = qtr * QTR;
    const int tid = threadIdx.x;
    for (int k = tid; k < Q * T / 4; k += 256)
        reinterpret_cast<float4*>(Ws)[k] =
            reinterpret_cast<const float4*>(g_W + (size_t)h * Q * T)[k];
    for (int k = tid; k < Q * QTR / 4; k += 256) {
        int q = k >> 5, c4 = k & 31;
        *reinterpret_cast<float4*>(&locS[q * CBPQ + c4 * 4]) =
            *reinterpret_cast<const float4*>(&g_loc[((size_t)h * Q + q) * CB + cbh + c4 * 4]);
    }
    __syncthreads();
    {
        int n = tid >> 3, b = tid & 7;
        float aRe = g_dATre[h * 32 + n], aIm = g_dATim[h * 32 + n];
        float cre = 0.0f, cim = 0.0f;
        if (qtr > 0) {
            cre = g_qre[(h * 32 + n) * 32 + (qtr - 1) * 8 + b];
            cim = g_qim[(h * 32 + n) * 32 + (qtr - 1) * 8 + b];
        }
        float* pr = &locS[n * CBPQ + b];
        float* pi = &locS[(32 + n) * CBPQ + b];
        #pragma unroll 4
        for (int c = 0; c < NCQ; ++c) {
            float lre = pr[c * 8], lim = pi[c * 8];
            pr[c * 8] = cre; pi[c * 8] = cim;
            float nre = fmaf(aRe, cre, fmaf(-aIm, cim, lre));
            float nim = fmaf(aIm, cre, fmaf(aRe, cim, lim));
            cre = nre; cim = nim;
        }
        if (qtr == 3 && stateMode > 0) {
            size_t ysEnd = (size_t)B * L * Hd;
            size_t idx = ((size_t)b * Hd + h) * N2 + n;
            out[ysEnd + idx] = cre;
            if (stateMode > 1) out[ysEnd + (size_t)B * Hd * N2 + idx] = cim;
        }
    }
    __syncthreads();
    const int cc = tid & 31, w = tid >> 5, t0 = w * 8;
    u64 acc[4][4];
    #pragma unroll
    for (int a = 0; a < 4; ++a)
        #pragma unroll
        for (int p = 0; p < 4; ++p) acc[a][p] = 0ull;
    #pragma unroll 4
    for (int q = 0; q < Q; ++q) {
        float4 sv = *reinterpret_cast<const float4*>(&locS[q * CBPQ + cc * 4]);
        ulonglong2 wa = *reinterpret_cast<const ulonglong2*>(&Ws[q * T + t0]);
        ulonglong2 wb = *reinterpret_cast<const ulonglong2*>(&Ws[q * T + t0 + 4]);
        u64 xx;
        xx = pk2(sv.x, sv.x);
        acc[0][0] = fma2(wa.x, xx, acc[0][0]); acc[0][1] = fma2(wa.y, xx, acc[0][1]);
        acc[0][2] = fma2(wb.x, xx, acc[0][2]); acc[0][3] = fma2(wb.y, xx, acc[0][3]);
        xx = pk2(sv.y, sv.y);
        acc[1][0] = fma2(wa.x, xx, acc[1][0]); acc[1][1] = fma2(wa.y, xx, acc[1][1]);
        acc[1][2] = fma2(wb.x, xx, acc[1][2]); acc[1][3] = fma2(wb.y, xx, acc[1][3]);
        xx = pk2(sv.z, sv.z);
        acc[2][0] = fma2(wa.x, xx, acc[2][0]); acc[2][1] = fma2(wa.y, xx, acc[2][1]);
        acc[2][2] = fma2(wb.x, xx, acc[2][2]); acc[2][3] = fma2(wb.y, xx, acc[2][3]);
        xx = pk2(sv.w, sv.w);
        acc[3][0] = fma2(wa.x, xx, acc[3][0]); acc[3][1] = fma2(wa.y, xx, acc[3][1]);
        acc[3][2] = fma2(wb.x, xx, acc[3][2]); acc[3][3] = fma2(wb.y, xx, acc[3][3]);
    }
    #pragma unroll
    for (int rnd = 0; rnd < 2; ++rnd) {
        if ((cc >> 4) == rnd) {
            #pragma unroll
            for (int a = 0; a < 4; ++a) {
                float* row = &stg[(cc * 4 + a - rnd * 64) * STP + t0];
                #pragma unroll
                for (int p = 0; p < 4; ++p) {
                    float2 f = upk2(acc[a][p]);
                    *reinterpret_cast<float2*>(&row[2 * p]) = f;
                }
            }
        }
        __syncthreads();
        for (int k = tid; k < 64 * T / 4; k += 256) {
            int r = k >> 4, tp = (k & 15) * 4;
            float2 a2 = *reinterpret_cast<const float2*>(&stg[r * STP + tp]);
            float2 b2 = *reinterpret_cast<const float2*>(&stg[r * STP + tp + 2]);
            *reinterpret_cast<float4*>(
                &g_corr[((size_t)h * CB + cbh + rnd * 64 + r) * T + tp]) =
                make_float4(a2.x, a2.y, b2.x, b2.y);
        }
        __syncthreads();
    }
}

// ---------------------------------------------------------------------------
// K4: output = causal conv(K,x) + corr + D*x, then exact GELU.
// Pair-balanced (9 tiles/warp) with SLIM x buffers: only 7 pad rows are ever
// read (rb_min = 56 in old indexing), so xs rows = 7 pad + 64 x = 71.
// x[t] lives at row 7+t; tile base rb = t0 - l0 (>= 0).
// grid (CB/NCC, Hd/32), block 256, dynamic smem 43.1KB.
// ---------------------------------------------------------------------------
__global__ void __launch_bounds__(256) k_out(const float* __restrict__ x,
                                             const float* __restrict__ Dv,
                                             float* __restrict__ out) {
    extern __shared__ float smo[];
    float* xs0 = smo;                      // [32*XSP]
    float* xs1 = smo + 32 * XSP;
    float* Ks  = smo + 2 * 32 * XSP;       // [32*65]
    float* cs0 = Ks + 32 * 65;             // [32*65]
    float* cs1 = cs0 + 32 * 65;
    const int h0 = blockIdx.y * 32;
    const int tid = threadIdx.x;
    const int hh = tid & 31, w = tid >> 5;
    // one-time: zero pads (rows 0..6) + K table
    for (int k = tid; k < 32 * 7; k += 256) {
        int h2 = k & 31, r = k >> 5;
        xs0[h2 * XSP + r] = 0.0f;
        xs1[h2 * XSP + r] = 0.0f;
    }
    for (int k = tid; k < 32 * 64; k += 256) {
        int h2 = k & 31, l = k >> 5;
        Ks[h2 * 65 + l] = g_K[(h0 + h2) * T + l];
    }
    const float Dh = Dv[h0 + hh];
    const float* krow = &Ks[hh * 65];

    for (int pi = 0; pi < NCC / 2; ++pi) {
        const int cbA = blockIdx.x * NCC + 2 * pi;
        const int cbB = cbA + 1;
        const int bA = cbA & 7, cA = cbA >> 3;
        const int bB = cbB & 7, cB = cbB >> 3;
        __syncthreads();   // previous pair's compute done before overwriting
        for (int k = tid; k < 32 * 64; k += 256) {
            int h2 = k & 31, tt = k >> 5;
            xs0[h2 * XSP + 7 + tt] = x[((size_t)bA * L + cA * T + tt) * Hd + h0 + h2];
            xs1[h2 * XSP + 7 + tt] = x[((size_t)bB * L + cB * T + tt) * Hd + h0 + h2];
        }
        for (int k = tid; k < 2048; k += 256) {
            int h2 = k >> 6, tt = k & 63;
            cs0[h2 * 65 + tt] = g_corr[((size_t)(h0 + h2) * CB + cbA) * T + tt];
            cs1[h2 * 65 + tt] = g_corr[((size_t)(h0 + h2) * CB + cbB) * T + tt];
        }
        __syncthreads();

        #pragma unroll
        for (int e = 0; e < 2; ++e) {
            const int o  = e == 0 ? w : 7 - w;      // octet for this element
            const int t0 = o * 8;
            const float* xrow = (e == 0 ? xs0 : xs1) + hh * XSP;
            const float* crow = (e == 0 ? cs0 : cs1) + hh * 65;
            const int b = e == 0 ? bA : bB;
            const int c = e == 0 ? cA : cB;

            u64 accp[4];
            #pragma unroll
            for (int p = 0; p < 4; ++p)
                accp[p] = pk2(crow[t0 + 2 * p], crow[t0 + 2 * p + 1]);

            for (int lt = 0; lt <= o; ++lt) {
                const int l0 = lt * 8;
                const int rb = t0 - l0;             // slim-layout window base
                float xw[15];
                #pragma unroll
                for (int j = 0; j < 15; ++j) xw[j] = xrow[rb + j];
                u64 xwp[14];
                #pragma unroll
                for (int a = 0; a < 14; ++a) xwp[a] = pk2(xw[a], xw[a + 1]);
                #pragma unroll
                for (int i = 0; i < 8; ++i) {
                    float kv = krow[l0 + i];
                    u64 k2 = pk2(kv, kv);
                    accp[0] = fma2(k2, xwp[7 - i], accp[0]);
                    accp[1] = fma2(k2, xwp[9 - i], accp[1]);
                    accp[2] = fma2(k2, xwp[11 - i], accp[2]);
                    accp[3] = fma2(k2, xwp[13 - i], accp[3]);
                }
            }

            float acc[8];
            #pragma unroll
            for (int p = 0; p < 4; ++p) {
                float2 f = upk2(accp[p]);
                acc[2 * p] = f.x; acc[2 * p + 1] = f.y;
            }
            #pragma unroll
            for (int j = 0; j < 8; ++j) {
                float xv = xrow[7 + t0 + j];
                float yv = fmaf(Dh, xv, acc[j]);
                float g = 0.5f * yv * (1.0f + erff(yv * 0.70710678118654752f));
                out[((size_t)b * L + c * T + t0 + j) * Hd + h0 + hh] = g;
            }
        }
    }
}

// ---------------------------------------------------------------------------
// Launch
// ---------------------------------------------------------------------------
extern "C" void kernel_launch(void* const* d_in, const int* in_sizes, int n_in,
                              void* d_out, int out_size) {
    const float* x      = (const float*)d_in[0];
    const float* log_dt = (const float*)d_in[1];
    const float* arl    = (const float*)d_in[2];
    const float* aim    = (const float*)d_in[3];
    const float* Bre    = (const float*)d_in[4];
    const float* Bim    = (const float*)d_in[5];
    const float* Cre    = (const float*)d_in[6];
    const float* Cim    = (const float*)d_in[7];
    const float* Dv     = (const float*)d_in[8];
    float* out = (float*)d_out;

    const long long ysElems = (long long)B * L * Hd;   // 16,777,216
    const long long stN     = (long long)B * Hd * N2;  // 131,072
    int stateMode = 0;
    if ((long long)out_size >= ysElems + 2 * stN) stateMode = 2;
    else if ((long long)out_size >= ysElems + stN) stateMode = 1;

    const int locSmem  = (T * Q + T * XRP) * 4;                 // 50,176 B
    const int corrSmem = (Q * CBPQ + Q * T + 64 * STP) * 4;     // 67,072 B
    const int outSmem  = (2 * 32 * XSP + 3 * 32 * 65) * 4;      // 43,136 B
    static int attrDone = 0;
    if (!attrDone) {
        cudaFuncSetAttribute(k_loc, cudaFuncAttributeMaxDynamicSharedMemorySize, locSmem);
        cudaFuncSetAttribute(k_corrf, cudaFuncAttributeMaxDynamicSharedMemorySize, corrSmem);
        cudaFuncSetAttribute(k_out, cudaFuncAttributeMaxDynamicSharedMemorySize, outSmem);
        attrDone = 1;
    }

    k_prep<<<Hd, 32>>>(log_dt, arl, aim, Bre, Bim, Cre, Cim);
    k_tr<<<dim3(BL / 64, Hd / 64), 256>>>(x);
    k_loc<<<dim3(Hd, CB / 128), 256, locSmem>>>();
    k_mid<<<(HN * 8 + 255) / 256, 256>>>();
    k_corrf<<<dim3(Hd, 4), 256, corrSmem>>>(out, stateMode);
    k_out<<<dim3(CB / NCC, Hd / 32), 256, outSmem>>>(x, Dv, out);
}

// round 16
// speedup vs baseline: 1.0832x; 1.0200x over previous
#include <cuda_runtime.h>
#include <cuda_fp16.h>
#include <math.h>

// Problem constants
#define Hd 512
#define L 4096
#define B 8
#define N2 32
#define HN (Hd * N2)
#define T 64            // chunk length
#define NCH (L / T)     // 64 chunks per sequence
#define CB (NCH * B)    // 512 chunk-rows
#define Q 64            // 2*N2 (re block + im block)
#define BL (B * L)      // 32768
#define QTR (CB / 4)    // 128 cb per corr block
#define NCQ (NCH / 4)   // 16 chunks per quarter
#define CBPQ 132        // padded locS row stride (floats)
#define XRP 132         // padded xrs row stride
#define STP 66          // stg row stride
#define NCC 4           // chunks per k_out block (processed in pairs)
#define XSP 71          // slim xs row stride: 7 pad rows + 64 x rows

typedef unsigned long long u64;

__device__ __forceinline__ u64 pk2(float lo, float hi) {
    u64 r; asm("mov.b64 %0, {%1, %2};" : "=l"(r) : "f"(lo), "f"(hi)); return r;
}
__device__ __forceinline__ float2 upk2(u64 v) {
    float2 f; asm("mov.b64 {%0, %1}, %2;" : "=f"(f.x), "=f"(f.y) : "l"(v)); return f;
}
__device__ __forceinline__ u64 fma2(u64 a, u64 b, u64 c) {
    u64 d; asm("fma.rn.f32x2 %0, %1, %2, %3;" : "=l"(d) : "l"(a), "l"(b), "l"(c)); return d;
}

// ---------------------------------------------------------------------------
// Device-global parameter / scratch arrays
// ---------------------------------------------------------------------------
__device__ float g_dATre[HN], g_dATim[HN];                  // dA^T (double-derived)
__device__ __align__(16) float g_E[Hd * T * Q];             // [h][tau][q]: dA^{T-1-tau} dB
__device__ __align__(16) float g_W[Hd * Q * T];             // [h][q][t]
__device__ float g_K[Hd * T];                               // conv kernel
__device__ __align__(16) float g_xT[(size_t)Hd * BL];       // transposed x: [h][b*L+t]
__device__ __align__(16) float g_loc[(size_t)Hd * Q * CB];  // [h][q][cb]
__device__ __align__(16) __half g_corrh[(size_t)Hd * CB * T]; // [h][cb][t] fp16
__device__ float g_qre[HN * 32], g_qim[HN * 32];            // quarter carry-in states

// ---------------------------------------------------------------------------
// K0 (fused): per-h discretization, E table, W table (+transpose), K kernel.
// ---------------------------------------------------------------------------
__global__ void __launch_bounds__(32) k_prep(const float* __restrict__ log_dt,
                                             const float* __restrict__ arl,
                                             const float* __restrict__ aim,
                                             const float* __restrict__ Bre,
                                             const float* __restrict__ Bim,
                                             const float* __restrict__ Cre,
                                             const float* __restrict__ Cim) {
    __shared__ float wt[T * 68];   // [t][q]
    __shared__ float c2s[64];
    const int h = blockIdx.x;
    const int n = threadIdx.x;
    const int i = h * 32 + n;
    float dt   = expf(log_dt[h]);
    float are  = -expf(arl[i]);
    float aimv = aim[i];
    float zre = are * dt, zim = aimv * dt;
    float sz, cz; sincosf(zim, &sz, &cz);
    float ez = expf(zre);
    float dre = ez * cz, dimv = ez * sz;   // dA
    float sh = sinf(0.5f * zim);
    float em1re = expm1f(zre) * cz - 2.0f * sh * sh;
    float em1im = ez * sz;
    float inv = 1.0f / (are * are + aimv * aimv);
    float fre = (em1re * are + em1im * aimv) * inv;
    float fim = (em1im * are - em1re * aimv) * inv;
    float bre0 = Bre[i], bim0 = Bim[i];
    float dbre = bre0 * fre - bim0 * fim;
    float dbim = bre0 * fim + bim0 * fre;
    c2s[n]      =  2.0f * Cre[i];
    c2s[32 + n] = -2.0f * Cim[i];
    double zred = (double)are * (double)dt * (double)T;
    double zimd = (double)aimv * (double)dt * (double)T;
    double ezd = exp(zred);
    g_dATre[i] = (float)(ezd * cos(zimd));
    g_dATim[i] = (float)(ezd * sin(zimd));
    float pre = dbre, pim = dbim;
    float cre0 = Cre[i], cim0 = Cim[i];
    float wre = cre0 * dre - cim0 * dimv;
    float wim = cre0 * dimv + cim0 * dre;
    for (int l = 0; l < T; ++l) {
        g_E[((size_t)h * T + (T - 1 - l)) * Q + n]      = pre;
        g_E[((size_t)h * T + (T - 1 - l)) * Q + 32 + n] = pim;
        wt[l * 68 + n]      =  2.0f * wre;
        wt[l * 68 + 32 + n] = -2.0f * wim;
        float tre = pre * dre - pim * dimv; pim = pre * dimv + pim * dre; pre = tre;
        float ure = wre * dre - wim * dimv; wim = wre * dimv + wim * dre; wre = ure;
    }
    __syncthreads();
    // K[l] = sum_n (2Cre*E[T-1-l][n] - 2Cim*E[T-1-l][32+n])  (lane = l, 2 rounds)
    for (int l = n; l < T; l += 32) {
        const float* e = &g_E[((size_t)h * T + (T - 1 - l)) * Q];
        float s = 0.0f;
        #pragma unroll 8
        for (int m = 0; m < 32; ++m)
            s = fmaf(c2s[m], e[m], fmaf(c2s[32 + m], e[32 + m], s));
        g_K[h * T + l] = s;
    }
    // transpose wt [t][q] -> g_W [q][t]
    for (int k = n; k < Q * T / 4; k += 32) {
        int q = k >> 4, tq = (k & 15) * 4;
        float4 v = make_float4(wt[(tq + 0) * 68 + q], wt[(tq + 1) * 68 + q],
                               wt[(tq + 2) * 68 + q], wt[(tq + 3) * 68 + q]);
        *reinterpret_cast<float4*>(&g_W[((size_t)h * Q + q) * T + tq]) = v;
    }
}

// ---------------------------------------------------------------------------
// K-tr: transpose x [bt][h] -> xT [h][bt], 64x64 tiles, float4 global I/O
// ---------------------------------------------------------------------------
__global__ void __launch_bounds__(256) k_tr(const float* __restrict__ x) {
    __shared__ float tile[64 * 65];
    const int bt0 = blockIdx.x * 64;
    const int h0  = blockIdx.y * 64;
    const int tid = threadIdx.x;
    #pragma unroll
    for (int it = 0; it < 4; ++it) {
        int idx = tid + it * 256;           // [0,1024)
        int r = idx >> 4, q = idx & 15;
        float4 v = *reinterpret_cast<const float4*>(
            &x[(size_t)(bt0 + r) * Hd + h0 + q * 4]);
        float* tr = &tile[r * 65 + q * 4];
        tr[0] = v.x; tr[1] = v.y; tr[2] = v.z; tr[3] = v.w;
    }
    __syncthreads();
    #pragma unroll
    for (int it = 0; it < 4; ++it) {
        int idx = tid + it * 256;
        int hh = idx >> 4, rq = idx & 15;
        float4 v = make_float4(tile[(rq * 4 + 0) * 65 + hh],
                               tile[(rq * 4 + 1) * 65 + hh],
                               tile[(rq * 4 + 2) * 65 + hh],
                               tile[(rq * 4 + 3) * 65 + hh]);
        *reinterpret_cast<float4*>(&g_xT[(size_t)(h0 + hh) * BL + bt0 + rq * 4]) = v;
    }
}

// ---------------------------------------------------------------------------
// K1: loc[h][q][cb] = sum_tau E[h][tau][q] * x[cb][tau]
// ---------------------------------------------------------------------------
__global__ void __launch_bounds__(256) k_loc() {
    extern __shared__ float sm[];
    float* Es  = sm;                // [64][64] 16KB
    float* xrs = sm + T * Q;        // [64][XRP] 33.8KB
    const int h = blockIdx.x;
    const int cb0 = blockIdx.y * 128;
    const int tid = threadIdx.x;
    for (int k = tid; k < T * Q / 4; k += 256)
        reinterpret_cast<float4*>(Es)[k] =
            reinterpret_cast<const float4*>(g_E + (size_t)h * T * Q)[k];
    for (int k = tid; k < 128 * T; k += 256) {
        int c2 = k >> 6, tau = k & 63;
        int cb = cb0 + c2, b = cb & 7, c = cb >> 3;
        xrs[tau * XRP + c2] = g_xT[(size_t)h * BL + b * L + c * T + tau];
    }
    __syncthreads();
    const int cc = tid & 31, w = tid >> 5, q0 = w * 8;
    u64 acc[4][4];
    #pragma unroll
    for (int a = 0; a < 4; ++a)
        #pragma unroll
        for (int p = 0; p < 4; ++p) acc[a][p] = 0ull;
    #pragma unroll 4
    for (int tau = 0; tau < T; ++tau) {
        float4 xv = *reinterpret_cast<const float4*>(&xrs[tau * XRP + cc * 4]);
        ulonglong2 ea = *reinterpret_cast<const ulonglong2*>(&Es[tau * Q + q0]);
        ulonglong2 eb = *reinterpret_cast<const ulonglong2*>(&Es[tau * Q + q0 + 4]);
        u64 xx;
        xx = pk2(xv.x, xv.x);
        acc[0][0] = fma2(ea.x, xx, acc[0][0]); acc[0][1] = fma2(ea.y, xx, acc[0][1]);
        acc[0][2] = fma2(eb.x, xx, acc[0][2]); acc[0][3] = fma2(eb.y, xx, acc[0][3]);
        xx = pk2(xv.y, xv.y);
        acc[1][0] = fma2(ea.x, xx, acc[1][0]); acc[1][1] = fma2(ea.y, xx, acc[1][1]);
        acc[1][2] = fma2(eb.x, xx, acc[1][2]); acc[1][3] = fma2(eb.y, xx, acc[1][3]);
        xx = pk2(xv.z, xv.z);
        acc[2][0] = fma2(ea.x, xx, acc[2][0]); acc[2][1] = fma2(ea.y, xx, acc[2][1]);
        acc[2][2] = fma2(eb.x, xx, acc[2][2]); acc[2][3] = fma2(eb.y, xx, acc[2][3]);
        xx = pk2(xv.w, xv.w);
        acc[3][0] = fma2(ea.x, xx, acc[3][0]); acc[3][1] = fma2(ea.y, xx, acc[3][1]);
        acc[3][2] = fma2(eb.x, xx, acc[3][2]); acc[3][3] = fma2(eb.y, xx, acc[3][3]);
    }
    #pragma unroll
    for (int p = 0; p < 4; ++p) {
        float2 f0 = upk2(acc[0][p]), f1 = upk2(acc[1][p]);
        float2 f2 = upk2(acc[2][p]), f3 = upk2(acc[3][p]);
        int q = q0 + 2 * p;
        *reinterpret_cast<float4*>(&g_loc[((size_t)h * Q + q) * CB + cb0 + cc * 4]) =
            make_float4(f0.x, f1.x, f2.x, f3.x);
        *reinterpret_cast<float4*>(&g_loc[((size_t)h * Q + q + 1) * CB + cb0 + cc * 4]) =
            make_float4(f0.y, f1.y, f2.y, f3.y);
    }
}

// ---------------------------------------------------------------------------
// K-mid: quarter-boundary carry states.
// ---------------------------------------------------------------------------
__global__ void k_mid() {
    int i = blockIdx.x * 256 + threadIdx.x;   // [0, HN*8)
    if (i >= HN * 8) return;
    int b = i & 7, n = (i >> 3) & 31, h = i >> 8;
    float aRe = g_dATre[h * 32 + n], aIm = g_dATim[h * 32 + n];
    const float* gr = &g_loc[((size_t)h * Q + n) * CB + b];
    const float* gi = &g_loc[((size_t)h * Q + 32 + n) * CB + b];
    float cre = 0.0f, cim = 0.0f;
    #pragma unroll
    for (int qi = 0; qi < 3; ++qi) {
        #pragma unroll
        for (int c = 0; c < NCQ; ++c) {
            float lre = __ldg(gr + (qi * NCQ + c) * 8);
            float lim = __ldg(gi + (qi * NCQ + c) * 8);
            float nre = fmaf(aRe, cre, fmaf(-aIm, cim, lre));
            float nim = fmaf(aIm, cre, fmaf(aRe, cim, lim));
            cre = nre; cim = nim;
        }
        g_qre[(h * 32 + n) * 32 + qi * 8 + b] = cre;
        g_qim[(h * 32 + n) * 32 + qi * 8 + b] = cim;
    }
}

// ---------------------------------------------------------------------------
// K2: carry-scan (16 chunks) + correction GEMM per quarter. corr stored fp16.
// ---------------------------------------------------------------------------
__global__ void __launch_bounds__(256) k_corrf(float* __restrict__ out, int stateMode) {
    extern __shared__ float sm[];
    float* locS = sm;                    // 64*132 = 33.8KB
    float* Ws   = sm + Q * CBPQ;         // 16KB
    float* stg  = Ws + Q * T;            // 64*66 = 16.9KB
    const int h = blockIdx.x;
    const int qtr = blockIdx.y;
    const int cbh = qtr * QTR;
    const int tid = threadIdx.x;
    for (int k = tid; k < Q * T / 4; k += 256)
        reinterpret_cast<float4*>(Ws)[k] =
            reinterpret_cast<const float4*>(g_W + (size_t)h * Q * T)[k];
    for (int k = tid; k < Q * QTR / 4; k += 256) {
        int q = k >> 5, c4 = k & 31;
        *reinterpret_cast<float4*>(&locS[q * CBPQ + c4 * 4]) =
            *reinterpret_cast<const float4*>(&g_loc[((size_t)h * Q + q) * CB + cbh + c4 * 4]);
    }
    __syncthreads();
    {
        int n = tid >> 3, b = tid & 7;
        float aRe = g_dATre[h * 32 + n], aIm = g_dATim[h * 32 + n];
        float cre = 0.0f, cim = 0.0f;
        if (qtr > 0) {
            cre = g_qre[(h * 32 + n) * 32 + (qtr - 1) * 8 + b];
            cim = g_qim[(h * 32 + n) * 32 + (qtr - 1) * 8 + b];
        }
        float* pr = &locS[n * CBPQ + b];
        float* pi = &locS[(32 + n) * CBPQ + b];
        #pragma unroll 4
        for (int c = 0; c < NCQ; ++c) {
            float lre = pr[c * 8], lim = pi[c * 8];
            pr[c * 8] = cre; pi[c * 8] = cim;
            float nre = fmaf(aRe, cre, fmaf(-aIm, cim, lre));
            float nim = fmaf(aIm, cre, fmaf(aRe, cim, lim));
            cre = nre; cim = nim;
        }
        if (qtr == 3 && stateMode > 0) {
            size_t ysEnd = (size_t)B * L * Hd;
            size_t idx = ((size_t)b * Hd + h) * N2 + n;
            out[ysEnd + idx] = cre;
            if (stateMode > 1) out[ysEnd + (size_t)B * Hd * N2 + idx] = cim;
        }
    }
    __syncthreads();
    const int cc = tid & 31, w = tid >> 5, t0 = w * 8;
    u64 acc[4][4];
    #pragma unroll
    for (int a = 0; a < 4; ++a)
        #pragma unroll
        for (int p = 0; p < 4; ++p) acc[a][p] = 0ull;
    #pragma unroll 4
    for (int q = 0; q < Q; ++q) {
        float4 sv = *reinterpret_cast<const float4*>(&locS[q * CBPQ + cc * 4]);
        ulonglong2 wa = *reinterpret_cast<const ulonglong2*>(&Ws[q * T + t0]);
        ulonglong2 wb = *reinterpret_cast<const ulonglong2*>(&Ws[q * T + t0 + 4]);
        u64 xx;
        xx = pk2(sv.x, sv.x);
        acc[0][0] = fma2(wa.x, xx, acc[0][0]); acc[0][1] = fma2(wa.y, xx, acc[0][1]);
        acc[0][2] = fma2(wb.x, xx, acc[0][2]); acc[0][3] = fma2(wb.y, xx, acc[0][3]);
        xx = pk2(sv.y, sv.y);
        acc[1][0] = fma2(wa.x, xx, acc[1][0]); acc[1][1] = fma2(wa.y, xx, acc[1][1]);
        acc[1][2] = fma2(wb.x, xx, acc[1][2]); acc[1][3] = fma2(wb.y, xx, acc[1][3]);
        xx = pk2(sv.z, sv.z);
        acc[2][0] = fma2(wa.x, xx, acc[2][0]); acc[2][1] = fma2(wa.y, xx, acc[2][1]);
        acc[2][2] = fma2(wb.x, xx, acc[2][2]); acc[2][3] = fma2(wb.y, xx, acc[2][3]);
        xx = pk2(sv.w, sv.w);
        acc[3][0] = fma2(wa.x, xx, acc[3][0]); acc[3][1] = fma2(wa.y, xx, acc[3][1]);
        acc[3][2] = fma2(wb.x, xx, acc[3][2]); acc[3][3] = fma2(wb.y, xx, acc[3][3]);
    }
    #pragma unroll
    for (int rnd = 0; rnd < 2; ++rnd) {
        if ((cc >> 4) == rnd) {
            #pragma unroll
            for (int a = 0; a < 4; ++a) {
                float* row = &stg[(cc * 4 + a - rnd * 64) * STP + t0];
                #pragma unroll
                for (int p = 0; p < 4; ++p) {
                    float2 f = upk2(acc[a][p]);
                    *reinterpret_cast<float2*>(&row[2 * p]) = f;
                }
            }
        }
        __syncthreads();
        for (int k = tid; k < 64 * T / 4; k += 256) {
            int r = k >> 4, tp = (k & 15) * 4;
            float2 a2 = *reinterpret_cast<const float2*>(&stg[r * STP + tp]);
            float2 b2 = *reinterpret_cast<const float2*>(&stg[r * STP + tp + 2]);
            __half2* cp = reinterpret_cast<__half2*>(
                &g_corrh[((size_t)h * CB + cbh + rnd * 64 + r) * T + tp]);
            cp[0] = __floats2half2_rn(a2.x, a2.y);
            cp[1] = __floats2half2_rn(b2.x, b2.y);
        }
        __syncthreads();
    }
}

// ---------------------------------------------------------------------------
// K4: output = causal conv(K,x) + corr + D*x, then exact GELU.
// Pair-balanced (9 tiles/warp), slim xs, NO corr smem staging: each thread
// loads its own 8 fp16 corr values (16B contiguous) into the accumulator
// init. smem = 26.5KB -> high occupancy.
// ---------------------------------------------------------------------------
__global__ void __launch_bounds__(256) k_out(const float* __restrict__ x,
                                             const float* __restrict__ Dv,
                                             float* __restrict__ out) {
    extern __shared__ float smo[];
    float* xs0 = smo;                      // [32*XSP]
    float* xs1 = smo + 32 * XSP;
    float* Ks  = smo + 2 * 32 * XSP;       // [32*65]
    const int h0 = blockIdx.y * 32;
    const int tid = threadIdx.x;
    const int hh = tid & 31, w = tid >> 5;
    for (int k = tid; k < 32 * 7; k += 256) {
        int h2 = k & 31, r = k >> 5;
        xs0[h2 * XSP + r] = 0.0f;
        xs1[h2 * XSP + r] = 0.0f;
    }
    for (int k = tid; k < 32 * 64; k += 256) {
        int h2 = k & 31, l = k >> 5;
        Ks[h2 * 65 + l] = g_K[(h0 + h2) * T + l];
    }
    const float Dh = Dv[h0 + hh];
    const float* krow = &Ks[hh * 65];

    for (int pi = 0; pi < NCC / 2; ++pi) {
        const int cbA = blockIdx.x * NCC + 2 * pi;
        const int cbB = cbA + 1;
        const int bA = cbA & 7, cA = cbA >> 3;
        const int bB = cbB & 7, cB = cbB >> 3;
        __syncthreads();   // previous pair's compute done before overwriting
        for (int k = tid; k < 32 * 64; k += 256) {
            int h2 = k & 31, tt = k >> 5;
            xs0[h2 * XSP + 7 + tt] = x[((size_t)bA * L + cA * T + tt) * Hd + h0 + h2];
            xs1[h2 * XSP + 7 + tt] = x[((size_t)bB * L + cB * T + tt) * Hd + h0 + h2];
        }
        __syncthreads();

        #pragma unroll
        for (int e = 0; e < 2; ++e) {
            const int o  = e == 0 ? w : 7 - w;      // octet for this element
            const int t0 = o * 8;
            const float* xrow = (e == 0 ? xs0 : xs1) + hh * XSP;
            const int cb = e == 0 ? cbA : cbB;
            const int b = e == 0 ? bA : bB;
            const int c = e == 0 ? cA : cB;

            // direct fp16 corr load: 8 halfs = 16B contiguous, aligned
            const __half2* cp = reinterpret_cast<const __half2*>(
                &g_corrh[((size_t)(h0 + hh) * CB + cb) * T + t0]);
            u64 accp[4];
            #pragma unroll
            for (int p = 0; p < 4; ++p) {
                float2 f = __half22float2(cp[p]);
                accp[p] = pk2(f.x, f.y);
            }

            for (int lt = 0; lt <= o; ++lt) {
                const int l0 = lt * 8;
                const int rb = t0 - l0;             // slim-layout window base
                float xw[15];
                #pragma unroll
                for (int j = 0; j < 15; ++j) xw[j] = xrow[rb + j];
                u64 xwp[14];
                #pragma unroll
                for (int a = 0; a < 14; ++a) xwp[a] = pk2(xw[a], xw[a + 1]);
                #pragma unroll
                for (int i = 0; i < 8; ++i) {
                    float kv = krow[l0 + i];
                    u64 k2 = pk2(kv, kv);
                    accp[0] = fma2(k2, xwp[7 - i], accp[0]);
                    accp[1] = fma2(k2, xwp[9 - i], accp[1]);
                    accp[2] = fma2(k2, xwp[11 - i], accp[2]);
                    accp[3] = fma2(k2, xwp[13 - i], accp[3]);
                }
            }

            float acc[8];
            #pragma unroll
            for (int p = 0; p < 4; ++p) {
                float2 f = upk2(accp[p]);
                acc[2 * p] = f.x; acc[2 * p + 1] = f.y;
            }
            #pragma unroll
            for (int j = 0; j < 8; ++j) {
                float xv = xrow[7 + t0 + j];
                float yv = fmaf(Dh, xv, acc[j]);
                float g = 0.5f * yv * (1.0f + erff(yv * 0.70710678118654752f));
                out[((size_t)b * L + c * T + t0 + j) * Hd + h0 + hh] = g;
            }
        }
    }
}

// ---------------------------------------------------------------------------
// Launch
// ---------------------------------------------------------------------------
extern "C" void kernel_launch(void* const* d_in, const int* in_sizes, int n_in,
                              void* d_out, int out_size) {
    const float* x      = (const float*)d_in[0];
    const float* log_dt = (const float*)d_in[1];
    const float* arl    = (const float*)d_in[2];
    const float* aim    = (const float*)d_in[3];
    const float* Bre    = (const float*)d_in[4];
    const float* Bim    = (const float*)d_in[5];
    const float* Cre    = (const float*)d_in[6];
    const float* Cim    = (const float*)d_in[7];
    const float* Dv     = (const float*)d_in[8];
    float* out = (float*)d_out;

    const long long ysElems = (long long)B * L * Hd;   // 16,777,216
    const long long stN     = (long long)B * Hd * N2;  // 131,072
    int stateMode = 0;
    if ((long long)out_size >= ysElems + 2 * stN) stateMode = 2;
    else if ((long long)out_size >= ysElems + stN) stateMode = 1;

    const int locSmem  = (T * Q + T * XRP) * 4;                 // 50,176 B
    const int corrSmem = (Q * CBPQ + Q * T + 64 * STP) * 4;     // 67,072 B
    const int outSmem  = (2 * 32 * XSP + 32 * 65) * 4;          // 26,496 B
    static int attrDone = 0;
    if (!attrDone) {
        cudaFuncSetAttribute(k_loc, cudaFuncAttributeMaxDynamicSharedMemorySize, locSmem);
        cudaFuncSetAttribute(k_corrf, cudaFuncAttributeMaxDynamicSharedMemorySize, corrSmem);
        cudaFuncSetAttribute(k_out, cudaFuncAttributeMaxDynamicSharedMemorySize, outSmem);
        attrDone = 1;
    }

    k_prep<<<Hd, 32>>>(log_dt, arl, aim, Bre, Bim, Cre, Cim);
    k_tr<<<dim3(BL / 64, Hd / 64), 256>>>(x);
    k_loc<<<dim3(Hd, CB / 128), 256, locSmem>>>();
    k_mid<<<(HN * 8 + 255) / 256, 256>>>();
    k_corrf<<<dim3(Hd, 4), 256, corrSmem>>>(out, stateMode);
    k_out<<<dim3(CB / NCC, Hd / 32), 256, outSmem>>>(x, Dv, out);
}

// round 17
// speedup vs baseline: 1.0836x; 1.0004x over previous
#include <cuda_runtime.h>
#include <cuda_fp16.h>
#include <math.h>

// Problem constants
#define Hd 512
#define L 4096
#define B 8
#define N2 32
#define HN (Hd * N2)
#define T 64            // chunk length
#define NCH (L / T)     // 64 chunks per sequence
#define CB (NCH * B)    // 512 chunk-rows
#define Q 64            // 2*N2 (re block + im block)
#define BL (B * L)      // 32768
#define QTR (CB / 4)    // 128 cb per corr block
#define NCQ (NCH / 4)   // 16 chunks per quarter
#define CBPQ 132        // padded locS row stride (floats)
#define XRP 132         // padded xrs row stride
#define STP 66          // stg row stride
#define NCC 8           // chunks per k_out block (processed in pairs)
#define XSP 71          // slim xs row stride: 7 pad rows + 64 x rows

typedef unsigned long long u64;

__device__ __forceinline__ u64 pk2(float lo, float hi) {
    u64 r; asm("mov.b64 %0, {%1, %2};" : "=l"(r) : "f"(lo), "f"(hi)); return r;
}
__device__ __forceinline__ float2 upk2(u64 v) {
    float2 f; asm("mov.b64 {%0, %1}, %2;" : "=f"(f.x), "=f"(f.y) : "l"(v)); return f;
}
__device__ __forceinline__ u64 fma2(u64 a, u64 b, u64 c) {
    u64 d; asm("fma.rn.f32x2 %0, %1, %2, %3;" : "=l"(d) : "l"(a), "l"(b), "l"(c)); return d;
}

// ---------------------------------------------------------------------------
// Device-global parameter / scratch arrays
// ---------------------------------------------------------------------------
__device__ float g_dATre[HN], g_dATim[HN];                  // dA^T (double-derived)
__device__ __align__(16) float g_E[Hd * T * Q];             // [h][tau][q]: dA^{T-1-tau} dB
__device__ __align__(16) float g_W[Hd * Q * T];             // [h][q][t]
__device__ float g_K[Hd * T];                               // conv kernel
__device__ __align__(16) float g_xT[(size_t)Hd * BL];       // transposed x: [h][b*L+t]
__device__ __align__(16) __half g_loch[(size_t)Hd * Q * CB];  // [h][q][cb] fp16
__device__ __align__(16) __half g_corrh[(size_t)Hd * CB * T]; // [h][cb][t] fp16
__device__ float g_qre[HN * 32], g_qim[HN * 32];            // quarter carry-in states

// ---------------------------------------------------------------------------
// K0 (fused): per-h discretization, E table, W table (+transpose), K kernel.
// ---------------------------------------------------------------------------
__global__ void __launch_bounds__(32) k_prep(const float* __restrict__ log_dt,
                                             const float* __restrict__ arl,
                                             const float* __restrict__ aim,
                                             const float* __restrict__ Bre,
                                             const float* __restrict__ Bim,
                                             const float* __restrict__ Cre,
                                             const float* __restrict__ Cim) {
    __shared__ float wt[T * 68];   // [t][q]
    __shared__ float c2s[64];
    const int h = blockIdx.x;
    const int n = threadIdx.x;
    const int i = h * 32 + n;
    float dt   = expf(log_dt[h]);
    float are  = -expf(arl[i]);
    float aimv = aim[i];
    float zre = are * dt, zim = aimv * dt;
    float sz, cz; sincosf(zim, &sz, &cz);
    float ez = expf(zre);
    float dre = ez * cz, dimv = ez * sz;   // dA
    float sh = sinf(0.5f * zim);
    float em1re = expm1f(zre) * cz - 2.0f * sh * sh;
    float em1im = ez * sz;
    float inv = 1.0f / (are * are + aimv * aimv);
    float fre = (em1re * are + em1im * aimv) * inv;
    float fim = (em1im * are - em1re * aimv) * inv;
    float bre0 = Bre[i], bim0 = Bim[i];
    float dbre = bre0 * fre - bim0 * fim;
    float dbim = bre0 * fim + bim0 * fre;
    c2s[n]      =  2.0f * Cre[i];
    c2s[32 + n] = -2.0f * Cim[i];
    double zred = (double)are * (double)dt * (double)T;
    double zimd = (double)aimv * (double)dt * (double)T;
    double ezd = exp(zred);
    g_dATre[i] = (float)(ezd * cos(zimd));
    g_dATim[i] = (float)(ezd * sin(zimd));
    float pre = dbre, pim = dbim;
    float cre0 = Cre[i], cim0 = Cim[i];
    float wre = cre0 * dre - cim0 * dimv;
    float wim = cre0 * dimv + cim0 * dre;
    for (int l = 0; l < T; ++l) {
        g_E[((size_t)h * T + (T - 1 - l)) * Q + n]      = pre;
        g_E[((size_t)h * T + (T - 1 - l)) * Q + 32 + n] = pim;
        wt[l * 68 + n]      =  2.0f * wre;
        wt[l * 68 + 32 + n] = -2.0f * wim;
        float tre = pre * dre - pim * dimv; pim = pre * dimv + pim * dre; pre = tre;
        float ure = wre * dre - wim * dimv; wim = wre * dimv + wim * dre; wre = ure;
    }
    __syncthreads();
    // K[l] = sum_n (2Cre*E[T-1-l][n] - 2Cim*E[T-1-l][32+n])
    for (int l = n; l < T; l += 32) {
        const float* e = &g_E[((size_t)h * T + (T - 1 - l)) * Q];
        float s = 0.0f;
        #pragma unroll 8
        for (int m = 0; m < 32; ++m)
            s = fmaf(c2s[m], e[m], fmaf(c2s[32 + m], e[32 + m], s));
        g_K[h * T + l] = s;
    }
    // transpose wt [t][q] -> g_W [q][t]
    for (int k = n; k < Q * T / 4; k += 32) {
        int q = k >> 4, tq = (k & 15) * 4;
        float4 v = make_float4(wt[(tq + 0) * 68 + q], wt[(tq + 1) * 68 + q],
                               wt[(tq + 2) * 68 + q], wt[(tq + 3) * 68 + q]);
        *reinterpret_cast<float4*>(&g_W[((size_t)h * Q + q) * T + tq]) = v;
    }
}

// ---------------------------------------------------------------------------
// K-tr: transpose x [bt][h] -> xT [h][bt], 64x64 tiles, float4 global I/O
// ---------------------------------------------------------------------------
__global__ void __launch_bounds__(256) k_tr(const float* __restrict__ x) {
    __shared__ float tile[64 * 65];
    const int bt0 = blockIdx.x * 64;
    const int h0  = blockIdx.y * 64;
    const int tid = threadIdx.x;
    #pragma unroll
    for (int it = 0; it < 4; ++it) {
        int idx = tid + it * 256;           // [0,1024)
        int r = idx >> 4, q = idx & 15;
        float4 v = *reinterpret_cast<const float4*>(
            &x[(size_t)(bt0 + r) * Hd + h0 + q * 4]);
        float* tr = &tile[r * 65 + q * 4];
        tr[0] = v.x; tr[1] = v.y; tr[2] = v.z; tr[3] = v.w;
    }
    __syncthreads();
    #pragma unroll
    for (int it = 0; it < 4; ++it) {
        int idx = tid + it * 256;
        int hh = idx >> 4, rq = idx & 15;
        float4 v = make_float4(tile[(rq * 4 + 0) * 65 + hh],
                               tile[(rq * 4 + 1) * 65 + hh],
                               tile[(rq * 4 + 2) * 65 + hh],
                               tile[(rq * 4 + 3) * 65 + hh]);
        *reinterpret_cast<float4*>(&g_xT[(size_t)(h0 + hh) * BL + bt0 + rq * 4]) = v;
    }
}

// ---------------------------------------------------------------------------
// K1: loc[h][q][cb] = sum_tau E[h][tau][q] * x[cb][tau]  (loc stored fp16)
// ---------------------------------------------------------------------------
__global__ void __launch_bounds__(256) k_loc() {
    extern __shared__ float sm[];
    float* Es  = sm;                // [64][64] 16KB
    float* xrs = sm + T * Q;        // [64][XRP] 33.8KB
    const int h = blockIdx.x;
    const int cb0 = blockIdx.y * 128;
    const int tid = threadIdx.x;
    for (int k = tid; k < T * Q / 4; k += 256)
        reinterpret_cast<float4*>(Es)[k] =
            reinterpret_cast<const float4*>(g_E + (size_t)h * T * Q)[k];
    for (int k = tid; k < 128 * T; k += 256) {
        int c2 = k >> 6, tau = k & 63;
        int cb = cb0 + c2, b = cb & 7, c = cb >> 3;
        xrs[tau * XRP + c2] = g_xT[(size_t)h * BL + b * L + c * T + tau];
    }
    __syncthreads();
    const int cc = tid & 31, w = tid >> 5, q0 = w * 8;
    u64 acc[4][4];
    #pragma unroll
    for (int a = 0; a < 4; ++a)
        #pragma unroll
        for (int p = 0; p < 4; ++p) acc[a][p] = 0ull;
    #pragma unroll 4
    for (int tau = 0; tau < T; ++tau) {
        float4 xv = *reinterpret_cast<const float4*>(&xrs[tau * XRP + cc * 4]);
        ulonglong2 ea = *reinterpret_cast<const ulonglong2*>(&Es[tau * Q + q0]);
        ulonglong2 eb = *reinterpret_cast<const ulonglong2*>(&Es[tau * Q + q0 + 4]);
        u64 xx;
        xx = pk2(xv.x, xv.x);
        acc[0][0] = fma2(ea.x, xx, acc[0][0]); acc[0][1] = fma2(ea.y, xx, acc[0][1]);
        acc[0][2] = fma2(eb.x, xx, acc[0][2]); acc[0][3] = fma2(eb.y, xx, acc[0][3]);
        xx = pk2(xv.y, xv.y);
        acc[1][0] = fma2(ea.x, xx, acc[1][0]); acc[1][1] = fma2(ea.y, xx, acc[1][1]);
        acc[1][2] = fma2(eb.x, xx, acc[1][2]); acc[1][3] = fma2(eb.y, xx, acc[1][3]);
        xx = pk2(xv.z, xv.z);
        acc[2][0] = fma2(ea.x, xx, acc[2][0]); acc[2][1] = fma2(ea.y, xx, acc[2][1]);
        acc[2][2] = fma2(eb.x, xx, acc[2][2]); acc[2][3] = fma2(eb.y, xx, acc[2][3]);
        xx = pk2(xv.w, xv.w);
        acc[3][0] = fma2(ea.x, xx, acc[3][0]); acc[3][1] = fma2(ea.y, xx, acc[3][1]);
        acc[3][2] = fma2(eb.x, xx, acc[3][2]); acc[3][3] = fma2(eb.y, xx, acc[3][3]);
    }
    #pragma unroll
    for (int p = 0; p < 4; ++p) {
        float2 f0 = upk2(acc[0][p]), f1 = upk2(acc[1][p]);
        float2 f2 = upk2(acc[2][p]), f3 = upk2(acc[3][p]);
        int q = q0 + 2 * p;
        __half2* lp0 = reinterpret_cast<__half2*>(
            &g_loch[((size_t)h * Q + q) * CB + cb0 + cc * 4]);
        lp0[0] = __floats2half2_rn(f0.x, f1.x);
        lp0[1] = __floats2half2_rn(f2.x, f3.x);
        __half2* lp1 = reinterpret_cast<__half2*>(
            &g_loch[((size_t)h * Q + q + 1) * CB + cb0 + cc * 4]);
        lp1[0] = __floats2half2_rn(f0.y, f1.y);
        lp1[1] = __floats2half2_rn(f2.y, f3.y);
    }
}

// ---------------------------------------------------------------------------
// K-mid: quarter-boundary carry states (reads fp16 loc).
// ---------------------------------------------------------------------------
__global__ void k_mid() {
    int i = blockIdx.x * 256 + threadIdx.x;   // [0, HN*8)
    if (i >= HN * 8) return;
    int b = i & 7, n = (i >> 3) & 31, h = i >> 8;
    float aRe = g_dATre[h * 32 + n], aIm = g_dATim[h * 32 + n];
    const __half* gr = &g_loch[((size_t)h * Q + n) * CB + b];
    const __half* gi = &g_loch[((size_t)h * Q + 32 + n) * CB + b];
    float cre = 0.0f, cim = 0.0f;
    #pragma unroll
    for (int qi = 0; qi < 3; ++qi) {
        #pragma unroll
        for (int c = 0; c < NCQ; ++c) {
            float lre = __half2float(__ldg(gr + (qi * NCQ + c) * 8));
            float lim = __half2float(__ldg(gi + (qi * NCQ + c) * 8));
            float nre = fmaf(aRe, cre, fmaf(-aIm, cim, lre));
            float nim = fmaf(aIm, cre, fmaf(aRe, cim, lim));
            cre = nre; cim = nim;
        }
        g_qre[(h * 32 + n) * 32 + qi * 8 + b] = cre;
        g_qim[(h * 32 + n) * 32 + qi * 8 + b] = cim;
    }
}

// ---------------------------------------------------------------------------
// K2: carry-scan (16 chunks) + correction GEMM per quarter.
// loc read fp16 -> fp32 smem; corr stored fp16.
// ---------------------------------------------------------------------------
__global__ void __launch_bounds__(256) k_corrf(float* __restrict__ out, int stateMode) {
    extern __shared__ float sm[];
    float* locS = sm;                    // 64*132 = 33.8KB
    float* Ws   = sm + Q * CBPQ;         // 16KB
    float* stg  = Ws + Q * T;            // 64*66 = 16.9KB
    const int h = blockIdx.x;
    const int qtr = blockIdx.y;
    const int cbh = qtr * QTR;
    const int tid = threadIdx.x;
    for (int k = tid; k < Q * T / 4; k += 256)
        reinterpret_cast<float4*>(Ws)[k] =
            reinterpret_cast<const float4*>(g_W + (size_t)h * Q * T)[k];
    for (int k = tid; k < Q * QTR / 8; k += 256) {
        int q = k >> 4, c8 = k & 15;
        const __half2* hp = reinterpret_cast<const __half2*>(
            &g_loch[((size_t)h * Q + q) * CB + cbh + c8 * 8]);
        float* dst = &locS[q * CBPQ + c8 * 8];
        #pragma unroll
        for (int u = 0; u < 4; ++u) {
            float2 f = __half22float2(hp[u]);
            dst[2 * u] = f.x; dst[2 * u + 1] = f.y;
        }
    }
    __syncthreads();
    {
        int n = tid >> 3, b = tid & 7;
        float aRe = g_dATre[h * 32 + n], aIm = g_dATim[h * 32 + n];
        float cre = 0.0f, cim = 0.0f;
        if (qtr > 0) {
            cre = g_qre[(h * 32 + n) * 32 + (qtr - 1) * 8 + b];
            cim = g_qim[(h * 32 + n) * 32 + (qtr - 1) * 8 + b];
        }
        float* pr = &locS[n * CBPQ + b];
        float* pi = &locS[(32 + n) * CBPQ + b];
        #pragma unroll 4
        for (int c = 0; c < NCQ; ++c) {
            float lre = pr[c * 8], lim = pi[c * 8];
            pr[c * 8] = cre; pi[c * 8] = cim;
            float nre = fmaf(aRe, cre, fmaf(-aIm, cim, lre));
            float nim = fmaf(aIm, cre, fmaf(aRe, cim, lim));
            cre = nre; cim = nim;
        }
        if (qtr == 3 && stateMode > 0) {
            size_t ysEnd = (size_t)B * L * Hd;
            size_t idx = ((size_t)b * Hd + h) * N2 + n;
            out[ysEnd + idx] = cre;
            if (stateMode > 1) out[ysEnd + (size_t)B * Hd * N2 + idx] = cim;
        }
    }
    __syncthreads();
    const int cc = tid & 31, w = tid >> 5, t0 = w * 8;
    u64 acc[4][4];
    #pragma unroll
    for (int a = 0; a < 4; ++a)
        #pragma unroll
        for (int p = 0; p < 4; ++p) acc[a][p] = 0ull;
    #pragma unroll 4
    for (int q = 0; q < Q; ++q) {
        float4 sv = *reinterpret_cast<const float4*>(&locS[q * CBPQ + cc * 4]);
        ulonglong2 wa = *reinterpret_cast<const ulonglong2*>(&Ws[q * T + t0]);
        ulonglong2 wb = *reinterpret_cast<const ulonglong2*>(&Ws[q * T + t0 + 4]);
        u64 xx;
        xx = pk2(sv.x, sv.x);
        acc[0][0] = fma2(wa.x, xx, acc[0][0]); acc[0][1] = fma2(wa.y, xx, acc[0][1]);
        acc[0][2] = fma2(wb.x, xx, acc[0][2]); acc[0][3] = fma2(wb.y, xx, acc[0][3]);
        xx = pk2(sv.y, sv.y);
        acc[1][0] = fma2(wa.x, xx, acc[1][0]); acc[1][1] = fma2(wa.y, xx, acc[1][1]);
        acc[1][2] = fma2(wb.x, xx, acc[1][2]); acc[1][3] = fma2(wb.y, xx, acc[1][3]);
        xx = pk2(sv.z, sv.z);
        acc[2][0] = fma2(wa.x, xx, acc[2][0]); acc[2][1] = fma2(wa.y, xx, acc[2][1]);
        acc[2][2] = fma2(wb.x, xx, acc[2][2]); acc[2][3] = fma2(wb.y, xx, acc[2][3]);
        xx = pk2(sv.w, sv.w);
        acc[3][0] = fma2(wa.x, xx, acc[3][0]); acc[3][1] = fma2(wa.y, xx, acc[3][1]);
        acc[3][2] = fma2(wb.x, xx, acc[3][2]); acc[3][3] = fma2(wb.y, xx, acc[3][3]);
    }
    #pragma unroll
    for (int rnd = 0; rnd < 2; ++rnd) {
        if ((cc >> 4) == rnd) {
            #pragma unroll
            for (int a = 0; a < 4; ++a) {
                float* row = &stg[(cc * 4 + a - rnd * 64) * STP + t0];
                #pragma unroll
                for (int p = 0; p < 4; ++p) {
                    float2 f = upk2(acc[a][p]);
                    *reinterpret_cast<float2*>(&row[2 * p]) = f;
                }
            }
        }
        __syncthreads();
        for (int k = tid; k < 64 * T / 4; k += 256) {
            int r = k >> 4, tp = (k & 15) * 4;
            float2 a2 = *reinterpret_cast<const float2*>(&stg[r * STP + tp]);
            float2 b2 = *reinterpret_cast<const float2*>(&stg[r * STP + tp + 2]);
            __half2* cp = reinterpret_cast<__half2*>(
                &g_corrh[((size_t)h * CB + cbh + rnd * 64 + r) * T + tp]);
            cp[0] = __floats2half2_rn(a2.x, a2.y);
            cp[1] = __floats2half2_rn(b2.x, b2.y);
        }
        __syncthreads();
    }
}

// ---------------------------------------------------------------------------
// K4: output = causal conv(K,x) + corr + D*x, then exact GELU.
// Pair-balanced (9 tiles/warp), slim xs, direct fp16 corr loads, NCC=8.
// ---------------------------------------------------------------------------
__global__ void __launch_bounds__(256) k_out(const float* __restrict__ x,
                                             const float* __restrict__ Dv,
                                             float* __restrict__ out) {
    extern __shared__ float smo[];
    float* xs0 = smo;                      // [32*XSP]
    float* xs1 = smo + 32 * XSP;
    float* Ks  = smo + 2 * 32 * XSP;       // [32*65]
    const int h0 = blockIdx.y * 32;
    const int tid = threadIdx.x;
    const int hh = tid & 31, w = tid >> 5;
    for (int k = tid; k < 32 * 7; k += 256) {
        int h2 = k & 31, r = k >> 5;
        xs0[h2 * XSP + r] = 0.0f;
        xs1[h2 * XSP + r] = 0.0f;
    }
    for (int k = tid; k < 32 * 64; k += 256) {
        int h2 = k & 31, l = k >> 5;
        Ks[h2 * 65 + l] = g_K[(h0 + h2) * T + l];
    }
    const float Dh = Dv[h0 + hh];
    const float* krow = &Ks[hh * 65];

    for (int pi = 0; pi < NCC / 2; ++pi) {
        const int cbA = blockIdx.x * NCC + 2 * pi;
        const int cbB = cbA + 1;
        const int bA = cbA & 7, cA = cbA >> 3;
        const int bB = cbB & 7, cB = cbB >> 3;
        __syncthreads();   // previous pair's compute done before overwriting
        for (int k = tid; k < 32 * 64; k += 256) {
            int h2 = k & 31, tt = k >> 5;
            xs0[h2 * XSP + 7 + tt] = x[((size_t)bA * L + cA * T + tt) * Hd + h0 + h2];
            xs1[h2 * XSP + 7 + tt] = x[((size_t)bB * L + cB * T + tt) * Hd + h0 + h2];
        }
        __syncthreads();

        #pragma unroll
        for (int e = 0; e < 2; ++e) {
            const int o  = e == 0 ? w : 7 - w;      // octet for this element
            const int t0 = o * 8;
            const float* xrow = (e == 0 ? xs0 : xs1) + hh * XSP;
            const int cb = e == 0 ? cbA : cbB;
            const int b = e == 0 ? bA : bB;
            const int c = e == 0 ? cA : cB;

            const __half2* cp = reinterpret_cast<const __half2*>(
                &g_corrh[((size_t)(h0 + hh) * CB + cb) * T + t0]);
            u64 accp[4];
            #pragma unroll
            for (int p = 0; p < 4; ++p) {
                float2 f = __half22float2(cp[p]);
                accp[p] = pk2(f.x, f.y);
            }

            for (int lt = 0; lt <= o; ++lt) {
                const int l0 = lt * 8;
                const int rb = t0 - l0;             // slim-layout window base
                float xw[15];
                #pragma unroll
                for (int j = 0; j < 15; ++j) xw[j] = xrow[rb + j];
                u64 xwp[14];
                #pragma unroll
                for (int a = 0; a < 14; ++a) xwp[a] = pk2(xw[a], xw[a + 1]);
                #pragma unroll
                for (int i = 0; i < 8; ++i) {
                    float kv = krow[l0 + i];
                    u64 k2 = pk2(kv, kv);
                    accp[0] = fma2(k2, xwp[7 - i], accp[0]);
                    accp[1] = fma2(k2, xwp[9 - i], accp[1]);
                    accp[2] = fma2(k2, xwp[11 - i], accp[2]);
                    accp[3] = fma2(k2, xwp[13 - i], accp[3]);
                }
            }

            float acc[8];
            #pragma unroll
            for (int p = 0; p < 4; ++p) {
                float2 f = upk2(accp[p]);
                acc[2 * p] = f.x; acc[2 * p + 1] = f.y;
            }
            #pragma unroll
            for (int j = 0; j < 8; ++j) {
                float xv = xrow[7 + t0 + j];
                float yv = fmaf(Dh, xv, acc[j]);
                float g = 0.5f * yv * (1.0f + erff(yv * 0.70710678118654752f));
                out[((size_t)b * L + c * T + t0 + j) * Hd + h0 + hh] = g;
            }
        }
    }
}

// ---------------------------------------------------------------------------
// Launch
// ---------------------------------------------------------------------------
extern "C" void kernel_launch(void* const* d_in, const int* in_sizes, int n_in,
                              void* d_out, int out_size) {
    const float* x      = (const float*)d_in[0];
    const float* log_dt = (const float*)d_in[1];
    const float* arl    = (const float*)d_in[2];
    const float* aim    = (const float*)d_in[3];
    const float* Bre    = (const float*)d_in[4];
    const float* Bim    = (const float*)d_in[5];
    const float* Cre    = (const float*)d_in[6];
    const float* Cim    = (const float*)d_in[7];
    const float* Dv     = (const float*)d_in[8];
    float* out = (float*)d_out;

    const long long ysElems = (long long)B * L * Hd;   // 16,777,216
    const long long stN     = (long long)B * Hd * N2;  // 131,072
    int stateMode = 0;
    if ((long long)out_size >= ysElems + 2 * stN) stateMode = 2;
    else if ((long long)out_size >= ysElems + stN) stateMode = 1;

    const int locSmem  = (T * Q + T * XRP) * 4;                 // 50,176 B
    const int corrSmem = (Q * CBPQ + Q * T + 64 * STP) * 4;     // 67,072 B
    const int outSmem  = (2 * 32 * XSP + 32 * 65) * 4;          // 26,496 B
    static int attrDone = 0;
    if (!attrDone) {
        cudaFuncSetAttribute(k_loc, cudaFuncAttributeMaxDynamicSharedMemorySize, locSmem);
        cudaFuncSetAttribute(k_corrf, cudaFuncAttributeMaxDynamicSharedMemorySize, corrSmem);
        cudaFuncSetAttribute(k_out, cudaFuncAttributeMaxDynamicSharedMemorySize, outSmem);
        attrDone = 1;
    }

    k_prep<<<Hd, 32>>>(log_dt, arl, aim, Bre, Bim, Cre, Cim);
    k_tr<<<dim3(BL / 64, Hd / 64), 256>>>(x);
    k_loc<<<dim3(Hd, CB / 128), 256, locSmem>>>();
    k_mid<<<(HN * 8 + 255) / 256, 256>>>();
    k_corrf<<<dim3(Hd, 4), 256, corrSmem>>>(out, stateMode);
    k_out<<<dim3(CB / NCC, Hd / 32), 256, outSmem>>>(x, Dv, out);
}